// round 16
// baseline (speedup 1.0000x reference)
#include <cuda_runtime.h>
#include <stdint.h>

// ---------------------------------------------------------------------------
// Persistent fp32 RNN, k-pair f32x2, j8xb4 tile, warp-specialized h/x warps.
//
// out[t] = tanh(x[t] @ Wi^T + h @ Wh^T),  h = out[t]
//
// 8 batch-groups x 16 H-slice CTAs = 128 CTAs, 384 threads (12 warps).
// Warps 0-7 ("h"): 32 h k-pairs each (full Wh reduction), reduce+store+
//   release+spin+readback. Warps 8-11 ("x"): 32 x k-pairs each; they stage
//   x(t+1) and compute the x-GEMM for t+1 DURING the h-warps' exchange,
//   keeping every SMSP's fma pipe busy through the serial window.
// Per-thread tile j8 x b4 with kh=lane>>4 row split; kh halves combined by
// shfl_xor(16). Ps[parity][b][ch*32+j], RSTR=390, rotated scatter
// (proven conflict-free). One __syncthreads per step; release via h-warp
// named barrier + tid0 fence.acq_rel.gpu + red.release (single increment).
// ---------------------------------------------------------------------------

namespace {
constexpr int kT = 1024, kB = 128, kI = 256, kH = 512;
constexpr int NG = 8, BG = 16, NC = 16, JC = 32;
constexpr int NTHR = 384;
constexpr int KP_H = kH / 2;          // 256
constexpr int KP_X = kI / 2;          // 128
constexpr int KPT  = KP_H + KP_X;     // 384

constexpr int WS_STRIDE = 34;         // u64 per weight row
constexpr int HD_STRIDE = 18;         // u64 per Hd row (16 cols + pad)
constexpr int PS_RSTR   = 390;        // floats per b-row (12*32 + pad)
constexpr int PS_PAR    = 16 * PS_RSTR;             // 6240 floats / parity

constexpr int OFF_WS = 0;
constexpr int OFF_HD = KPT * WS_STRIDE;             // 13056 u64
constexpr int OFF_PS = OFF_HD + KPT * HD_STRIDE;    // 19968 u64
constexpr int OFF_AUX = OFF_PS + PS_PAR;            // 2 parity bufs = 6240 u64
constexpr int SMEM_U64 = OFF_AUX + 1;               // 26209
constexpr size_t SMEM_BYTES = size_t(SMEM_U64) * 8; // 209672 B
}

__device__ unsigned g_rnn_flag[NG * NC];   // zero-init; monotonic forever

__device__ __forceinline__ void fma2(unsigned long long& acc,
                                     unsigned long long a,
                                     unsigned long long b) {
    asm("fma.rn.f32x2 %0, %1, %2, %0;" : "+l"(acc) : "l"(a), "l"(b));
}

// one k-pair row: 8 j (groups g0..g7 <-> j = 8jq + {0,1,4,5,2,3,6,7}) x 4 b
#define STEP32(wp, hp)                                                       \
    do {                                                                     \
        const ulonglong2 w0 = *reinterpret_cast<const ulonglong2*>(wp);      \
        const ulonglong2 w1 = *reinterpret_cast<const ulonglong2*>((wp)+2);  \
        const ulonglong2 w2 = *reinterpret_cast<const ulonglong2*>((wp)+16); \
        const ulonglong2 w3 = *reinterpret_cast<const ulonglong2*>((wp)+18); \
        const ulonglong2 h0 = *reinterpret_cast<const ulonglong2*>(hp);      \
        const ulonglong2 h1 = *reinterpret_cast<const ulonglong2*>((hp)+2);  \
        fma2(acc[0],  w0.x, h0.x); fma2(acc[1],  w0.x, h0.y);                \
        fma2(acc[2],  w0.x, h1.x); fma2(acc[3],  w0.x, h1.y);                \
        fma2(acc[4],  w0.y, h0.x); fma2(acc[5],  w0.y, h0.y);                \
        fma2(acc[6],  w0.y, h1.x); fma2(acc[7],  w0.y, h1.y);                \
        fma2(acc[8],  w1.x, h0.x); fma2(acc[9],  w1.x, h0.y);                \
        fma2(acc[10], w1.x, h1.x); fma2(acc[11], w1.x, h1.y);                \
        fma2(acc[12], w1.y, h0.x); fma2(acc[13], w1.y, h0.y);                \
        fma2(acc[14], w1.y, h1.x); fma2(acc[15], w1.y, h1.y);                \
        fma2(acc[16], w2.x, h0.x); fma2(acc[17], w2.x, h0.y);                \
        fma2(acc[18], w2.x, h1.x); fma2(acc[19], w2.x, h1.y);                \
        fma2(acc[20], w2.y, h0.x); fma2(acc[21], w2.y, h0.y);                \
        fma2(acc[22], w2.y, h1.x); fma2(acc[23], w2.y, h1.y);                \
        fma2(acc[24], w3.x, h0.x); fma2(acc[25], w3.x, h0.y);                \
        fma2(acc[26], w3.x, h1.x); fma2(acc[27], w3.x, h1.y);                \
        fma2(acc[28], w3.y, h0.x); fma2(acc[29], w3.y, h0.y);                \
        fma2(acc[30], w3.y, h1.x); fma2(acc[31], w3.y, h1.y);                \
    } while (0)

// combine lo+hi and kh-halves: sv[g*4+u] = full-K-chunk partial for (j,b)
__device__ __forceinline__ void combine_sv(float* sv,
                                           const unsigned long long* acc) {
    #pragma unroll
    for (int e = 0; e < 32; ++e) {
        float2 f = *reinterpret_cast<const float2*>(&acc[e]);
        float v = f.x + f.y;
        v += __shfl_xor_sync(0xffffffffu, v, 16);
        sv[e] = v;
    }
}

// scatter (lane<16 only): rotated u=(bi+jq)&3 -> STS.64 conflict-free
__device__ __forceinline__ void scatter_sv(float* Psb, const float* sv,
                                           int ch, int jq, int bp) {
    #pragma unroll
    for (int bi = 0; bi < 4; ++bi) {
        const int u = (bi + jq) & 3;
        float* dst = Psb + (4 * bp + u) * PS_RSTR + ch * 32 + 8 * jq;
        *reinterpret_cast<float2*>(dst + 0) = make_float2(sv[0 * 4 + u], sv[1 * 4 + u]);
        *reinterpret_cast<float2*>(dst + 2) = make_float2(sv[4 * 4 + u], sv[5 * 4 + u]);
        *reinterpret_cast<float2*>(dst + 4) = make_float2(sv[2 * 4 + u], sv[3 * 4 + u]);
        *reinterpret_cast<float2*>(dst + 6) = make_float2(sv[6 * 4 + u], sv[7 * 4 + u]);
    }
}

__global__ void __launch_bounds__(NTHR, 1)
rnn_wsx_kernel(const float* __restrict__ x,
               const float* __restrict__ Wi,
               const float* __restrict__ Wh,
               float* __restrict__ out,
               int write_tail)
{
    extern __shared__ unsigned long long smu[];
    unsigned long long* Ws = smu + OFF_WS;
    unsigned long long* Hd = smu + OFF_HD;
    float*              Ps = reinterpret_cast<float*>(smu + OFF_PS);
    unsigned*           Aux = reinterpret_cast<unsigned*>(smu + OFF_AUX);

    const int tid = threadIdx.x;
    const int g   = blockIdx.x >> 4;
    const int c   = blockIdx.x & 15;
    const int bg0 = g * BG;
    const int jg0 = c * JC;

    // ---- prologue: weights (column-permuted), zero h rows --------------------
    if (tid == 0) Aux[0] = g_rnn_flag[blockIdx.x];
    {
        const int jl  = tid & 31;
        const int kpb = tid >> 5;                 // 0..11
        const int dst = (jl >> 2) * 2 + ((jl >> 1) & 1) * 16 + (jl & 1);
        const float2* whp = reinterpret_cast<const float2*>(
            Wh + (size_t)(jg0 + jl) * kH);
        for (int kp = kpb; kp < KP_H; kp += 12) {
            float2 v = __ldg(whp + kp);
            Ws[kp * WS_STRIDE + dst] = *reinterpret_cast<unsigned long long*>(&v);
        }
        const float2* wip = reinterpret_cast<const float2*>(
            Wi + (size_t)(jg0 + jl) * kI);
        for (int kp = kpb; kp < KP_X; kp += 12) {
            float2 v = __ldg(wip + kp);
            Ws[(KP_H + kp) * WS_STRIDE + dst] =
                *reinterpret_cast<unsigned long long*>(&v);
        }
    }
    for (int e = tid; e < KP_H * HD_STRIDE; e += NTHR) Hd[e] = 0ull;
    __syncthreads();
    const unsigned base = Aux[0];

    // ---- geometry -------------------------------------------------------------
    const int w    = tid >> 5;             // warp 0..11
    const int lane = tid & 31;
    const bool hwarp = (w < 8);
    const int q    = w - 8;                // x-warp id 0..3
    const int jq   = lane & 3;
    const int bp   = (lane >> 2) & 3;

    // h readback roles (R13 geometry)
    const int p    = lane & 15;
    const int bh   = (lane >> 4) * 8;
    const int pge8 = (p >> 3) & 1;

    // x staging geometry: warp q stages rows [KP_H+32q, +32), lane -> 1 row
    const int xrow = KP_H + 32 * q + lane;
    const int xswz = 4 * ((lane >> 3) & 3);

    unsigned* myflag = g_rnn_flag + blockIdx.x;

    unsigned long long acc[32];
    float sv[32];

    // ---- x-warp prologue: stage x[0], x-GEMM(0) -> Ps[0] -----------------------
    if (!hwarp) {
        #pragma unroll
        for (int half = 0; half < 2; ++half) {
            float2 buf[8];
            #pragma unroll
            for (int i = 0; i < 8; ++i) {
                const int b = 8 * half + i;
                buf[i] = __ldcg(reinterpret_cast<const float2*>(
                    x + (size_t)(bg0 + b) * kI) + (32 * q + lane));
            }
            #pragma unroll
            for (int i = 0; i < 8; ++i) {
                const int b = 8 * half + i;
                Hd[(size_t)xrow * HD_STRIDE + (b ^ xswz)] =
                    *reinterpret_cast<unsigned long long*>(&buf[i]);
            }
        }
        __syncwarp();
        #pragma unroll
        for (int i = 0; i < 32; ++i) acc[i] = 0ull;
        const int kh = lane >> 4;
        #pragma unroll
        for (int s = 0; s < 4; ++s) {
            const unsigned long long* wp =
                Ws + (size_t)(KP_H + 32 * q + 8 * s + kh) * WS_STRIDE + 4 * jq;
            const unsigned long long* hp =
                Hd + (size_t)(KP_H + 32 * q + 8 * s + kh) * HD_STRIDE
                   + 4 * (bp ^ (s & 3));
            #pragma unroll
            for (int i = 0; i < 4; ++i) {
                STEP32(wp, hp);
                wp += 2 * WS_STRIDE; hp += 2 * HD_STRIDE;
            }
        }
        combine_sv(sv, acc);
        if (lane < 16) scatter_sv(Ps, sv, 8 + q, jq, bp);
    }

    // ---- main loop --------------------------------------------------------------
    for (int t = 0; t < kT; ++t) {
        if (hwarp) {
            // h-GEMM(t): rows [32w, 32w+32), kh-split
            #pragma unroll
            for (int i = 0; i < 32; ++i) acc[i] = 0ull;
            const int kh = lane >> 4;
            #pragma unroll
            for (int s = 0; s < 4; ++s) {
                const unsigned long long* wp =
                    Ws + (size_t)(32 * w + 8 * s + kh) * WS_STRIDE + 4 * jq;
                const unsigned long long* hp =
                    Hd + (size_t)(32 * w + 8 * s + kh) * HD_STRIDE
                       + 4 * (bp ^ (s & 3));
                #pragma unroll
                for (int i = 0; i < 4; ++i) {
                    STEP32(wp, hp);
                    wp += 2 * WS_STRIDE; hp += 2 * HD_STRIDE;
                }
            }
            combine_sv(sv, acc);
            if (lane < 16) scatter_sv(Ps + (t & 1) * PS_PAR, sv, w, jq, bp);
        } else if (t + 1 < kT) {
            // stage x(t+1) into own rows (read next iteration after S1)
            const float* xb = x + (size_t)(t + 1) * kB * kI;
            #pragma unroll
            for (int half = 0; half < 2; ++half) {
                float2 buf[8];
                #pragma unroll
                for (int i = 0; i < 8; ++i) {
                    const int b = 8 * half + i;
                    buf[i] = __ldcg(reinterpret_cast<const float2*>(
                        xb + (size_t)(bg0 + b) * kI) + (32 * q + lane));
                }
                #pragma unroll
                for (int i = 0; i < 8; ++i) {
                    const int b = 8 * half + i;
                    Hd[(size_t)xrow * HD_STRIDE + (b ^ xswz)] =
                        *reinterpret_cast<unsigned long long*>(&buf[i]);
                }
            }
        }

        __syncthreads();                                   // S1

        if (hwarp) {
            // ---- reduce 12 chunks, tanh, store out[t] --------------------------
            {
                const float* Psb = Ps + (t & 1) * PS_PAR;
                const int b  = tid >> 4;                   // 0..15 (256 threads)
                const int jp = tid & 15;
                float s0 = 0.f, s1 = 0.f;
                #pragma unroll
                for (int ch = 0; ch < 12; ++ch) {
                    float2 v = *reinterpret_cast<const float2*>(
                        Psb + b * PS_RSTR + ch * 32 + 2 * jp);
                    s0 += v.x; s1 += v.y;
                }
                float2 r2;
                r2.x = tanhf(s0);
                r2.y = tanhf(s1);
                size_t o = (size_t)t * kB * kH + (size_t)(bg0 + b) * kH
                         + jg0 + 2 * jp;
                *reinterpret_cast<float2*>(out + o) = r2;
                if (t == kT - 1 && write_tail)
                    *reinterpret_cast<float2*>(
                        out + (size_t)kT * kB * kH + (size_t)(bg0 + b) * kH
                            + jg0 + 2 * jp) = r2;
            }
            if (t + 1 < kT) {
                // ---- release once per CTA (h-warps-only barrier funnel) --------
                asm volatile("bar.sync 2, 256;" ::: "memory");
                if (tid == 0) {
                    asm volatile("fence.acq_rel.gpu;" ::: "memory");
                    asm volatile("red.release.gpu.global.add.u32 [%0], %1;"
                                 :: "l"(myflag), "r"(1u) : "memory");
                }
                // ---- wait 2 producers, readback + stage h(t+1) -----------------
                const unsigned target = base + (unsigned)(t + 1);
                #pragma unroll
                for (int qq = 0; qq < 2; ++qq) {
                    const int pcta = 2 * w + qq;
                    const unsigned* fp = g_rnn_flag + (g * NC + pcta);
                    unsigned cur;
                    do {
                        asm volatile("ld.acquire.gpu.global.u32 %0, [%1];"
                                     : "=r"(cur) : "l"(fp) : "memory");
                    } while ((int)(cur - target) < 0);

                    const int hswz = 4 * ((2 * pcta + pge8) & 3);
                    const float* hb = out + (size_t)t * kB * kH
                                          + (size_t)bg0 * kH + 32 * pcta + 2 * p;
                    float2 hv[8];
                    #pragma unroll
                    for (int i = 0; i < 8; ++i) {
                        const int brd = ((((2 * i) & 6) | (i >> 2)) ^ pge8);
                        hv[i] = __ldcg(reinterpret_cast<const float2*>(
                            hb + (size_t)(bh + brd) * kH));
                    }
                    #pragma unroll
                    for (int i = 0; i < 8; ++i) {
                        const int brd = ((((2 * i) & 6) | (i >> 2)) ^ pge8);
                        Hd[(16 * pcta + p) * HD_STRIDE + ((bh + brd) ^ hswz)] =
                            *reinterpret_cast<unsigned long long*>(&hv[i]);
                    }
                }
                __syncwarp();
            }
        } else if (t + 1 < kT) {
            // ---- x-GEMM(t+1): overlaps h-warps' exchange -----------------------
            #pragma unroll
            for (int i = 0; i < 32; ++i) acc[i] = 0ull;
            const int kh = lane >> 4;
            #pragma unroll
            for (int s = 0; s < 4; ++s) {
                const unsigned long long* wp =
                    Ws + (size_t)(KP_H + 32 * q + 8 * s + kh) * WS_STRIDE + 4 * jq;
                const unsigned long long* hp =
                    Hd + (size_t)(KP_H + 32 * q + 8 * s + kh) * HD_STRIDE
                       + 4 * (bp ^ (s & 3));
                #pragma unroll
                for (int i = 0; i < 4; ++i) {
                    STEP32(wp, hp);
                    wp += 2 * WS_STRIDE; hp += 2 * HD_STRIDE;
                }
            }
            combine_sv(sv, acc);
            if (lane < 16)
                scatter_sv(Ps + ((t + 1) & 1) * PS_PAR, sv, 8 + q, jq, bp);
        }
    }
}

extern "C" void kernel_launch(void* const* d_in, const int* in_sizes, int n_in,
                              void* d_out, int out_size) {
    const float* x  = (const float*)d_in[0];   // [T,B,I]
    const float* Wi = (const float*)d_in[1];   // [H,I]
    const float* Wh = (const float*)d_in[2];   // [H,H]
    float* out = (float*)d_out;

    const long long main_elems = (long long)kT * kB * kH;
    int write_tail = ((long long)out_size >= main_elems + (long long)kB * kH) ? 1 : 0;

    cudaFuncSetAttribute(rnn_wsx_kernel,
                         cudaFuncAttributeMaxDynamicSharedMemorySize,
                         (int)SMEM_BYTES);
    rnn_wsx_kernel<<<NG * NC, NTHR, SMEM_BYTES>>>(x, Wi, Wh, out, write_tail);
}